// round 5
// baseline (speedup 1.0000x reference)
#include <cuda_runtime.h>

#define NQ 6
#define DIM 64
#define NL 2
#define IN_DIM 4096
#define NH 32
#define B_TOTAL 32768

#define THREADS 512
#define WARPS 16
#define GRID 148
#define ROWS_PER_GROUP 4
#define NGROUPS (B_TOTAL / ROWS_PER_GROUP)

typedef unsigned long long u64;

// Precomputed batch-independent circuit matrix (transposed) and folded C.
__device__ float2 g_MT[DIM][DIM];   // g_MT[j][i] = M[i][j] (re,im)
__device__ float  g_CT[DIM][NH];    // C[i][h] = sum_w Wpost[h][w]*SIGNS[w][i]

// ---------------------------------------------------------------------------
// f32x2 helpers
// ---------------------------------------------------------------------------
__device__ __forceinline__ u64 pack2(float lo, float hi) {
    u64 r;
    asm("mov.b64 %0, {%1, %2};" : "=l"(r) : "f"(lo), "f"(hi));
    return r;
}
__device__ __forceinline__ void unpack2(u64 v, float& lo, float& hi) {
    asm("mov.b64 {%0, %1}, %2;" : "=f"(lo), "=f"(hi) : "l"(v));
}
__device__ __forceinline__ void fma2(u64& d, u64 a, u64 b) {
    asm("fma.rn.f32x2 %0, %1, %2, %0;" : "+l"(d) : "l"(a), "l"(b));
}

// ---------------------------------------------------------------------------
// Setup kernel — warp-register circuit sim. 16 warps x 4 columns, each warp
// keeps 4 column-states in registers (2 complex amps per lane per column),
// gates via shuffles. No __syncthreads at all. ~2us.
// ---------------------------------------------------------------------------
__global__ void setup_kernel(const float* __restrict__ qw,
                             const float* __restrict__ Wpost) {
    int tid  = threadIdx.x;
    int lane = tid & 31;
    int warp = tid >> 5;

    for (int cidx = 0; cidx < 4; cidx++) {
        int j = warp * 4 + cidx;   // column (initial basis state)
        // amplitudes: a0 = index lane, a1 = index lane+32
        float2 a0 = make_float2(lane == j ? 1.f : 0.f, 0.f);
        float2 a1 = make_float2(lane + 32 == j ? 1.f : 0.f, 0.f);

        for (int l = 0; l < NL; l++) {
            // Rot gates
            for (int w = 0; w < NQ; w++) {
                float phi = qw[(l * NQ + w) * 3 + 0];
                float th  = qw[(l * NQ + w) * 3 + 1];
                float om  = qw[(l * NQ + w) * 3 + 2];
                float ct = cosf(th * 0.5f), sn = sinf(th * 0.5f);
                float ap = (phi + om) * 0.5f, am = (phi - om) * 0.5f;
                float2 U00 = make_float2( ct * cosf(ap), -ct * sinf(ap));
                float2 U01 = make_float2(-sn * cosf(am), -sn * sinf(am));
                float2 U10 = make_float2( sn * cosf(am), -sn * sinf(am));
                float2 U11 = make_float2( ct * cosf(ap),  ct * sinf(ap));
                int m = 1 << (NQ - 1 - w);
                if (m == 32) {
                    // pair within thread: (lane, lane+32)
                    float2 n0 = make_float2(
                        U00.x * a0.x - U00.y * a0.y + U01.x * a1.x - U01.y * a1.y,
                        U00.x * a0.y + U00.y * a0.x + U01.x * a1.y + U01.y * a1.x);
                    float2 n1 = make_float2(
                        U10.x * a0.x - U10.y * a0.y + U11.x * a1.x - U11.y * a1.y,
                        U10.x * a0.y + U10.y * a0.x + U11.x * a1.y + U11.y * a1.x);
                    a0 = n0; a1 = n1;
                } else {
                    int p = lane ^ m;
                    float2 b0, b1;
                    b0.x = __shfl_sync(0xFFFFFFFFu, a0.x, p);
                    b0.y = __shfl_sync(0xFFFFFFFFu, a0.y, p);
                    b1.x = __shfl_sync(0xFFFFFFFFu, a1.x, p);
                    b1.y = __shfl_sync(0xFFFFFFFFu, a1.y, p);
                    bool hi = (lane & m) != 0;
                    float2 Ua = hi ? U11 : U00;   // coeff on own amp
                    float2 Ub = hi ? U10 : U01;   // coeff on partner amp
                    float2 n0 = make_float2(
                        Ua.x * a0.x - Ua.y * a0.y + Ub.x * b0.x - Ub.y * b0.y,
                        Ua.x * a0.y + Ua.y * a0.x + Ub.x * b0.y + Ub.y * b0.x);
                    float2 n1 = make_float2(
                        Ua.x * a1.x - Ua.y * a1.y + Ub.x * b1.x - Ub.y * b1.y,
                        Ua.x * a1.y + Ua.y * a1.x + Ub.x * b1.y + Ub.y * b1.x);
                    a0 = n0; a1 = n1;
                }
            }
            // CNOT ring (sequential): new[i] = old[(i&mc) ? i^mt : i]
            int r = l % (NQ - 1) + 1;
            for (int w = 0; w < NQ; w++) {
                int t = (w + r) % NQ;
                int mc = 1 << (NQ - 1 - w), mt = 1 << (NQ - 1 - t);
                int i0 = lane,      s0 = (i0 & mc) ? (i0 ^ mt) : i0;
                int i1 = lane + 32, s1 = (i1 & mc) ? (i1 ^ mt) : i1;
                float v00x = __shfl_sync(0xFFFFFFFFu, a0.x, s0 & 31);
                float v00y = __shfl_sync(0xFFFFFFFFu, a0.y, s0 & 31);
                float v01x = __shfl_sync(0xFFFFFFFFu, a1.x, s0 & 31);
                float v01y = __shfl_sync(0xFFFFFFFFu, a1.y, s0 & 31);
                float v10x = __shfl_sync(0xFFFFFFFFu, a0.x, s1 & 31);
                float v10y = __shfl_sync(0xFFFFFFFFu, a0.y, s1 & 31);
                float v11x = __shfl_sync(0xFFFFFFFFu, a1.x, s1 & 31);
                float v11y = __shfl_sync(0xFFFFFFFFu, a1.y, s1 & 31);
                a0 = (s0 >= 32) ? make_float2(v01x, v01y) : make_float2(v00x, v00y);
                a1 = (s1 >= 32) ? make_float2(v11x, v11y) : make_float2(v10x, v10y);
            }
        }
        g_MT[j][lane]      = a0;
        g_MT[j][lane + 32] = a1;
    }

    // C = W_post @ SIGNS, stored [i][h]
    for (int idx = tid; idx < DIM * NH; idx += THREADS) {
        int i = idx / NH, h = idx % NH;
        float s = 0.f;
        for (int w = 0; w < NQ; w++) {
            int bit = (i >> (NQ - 1 - w)) & 1;
            s += Wpost[h * NQ + w] * (1.f - 2.f * (float)bit);
        }
        g_CT[i][h] = s;
    }
}

// Shared memory layout (bytes):
//   Wsh  float[6*4096]      @      0   (98304)
//   Md   u64[64*64]         @  98304   (32768)
//   CTd  u64[64*32]         @ 131072   (16384)
//   Cbuf u64[16][256]       @ 147456   (32768)
#define SMEM_BYTES (98304 + 32768 + 16384 + 32768)

__global__ void __launch_bounds__(THREADS, 1)
qag_main(const float* __restrict__ sv, const float* __restrict__ Wang,
         const float* __restrict__ bang, const float* __restrict__ bpost,
         float* __restrict__ out) {
    extern __shared__ __align__(16) char smem_raw[];
    float* Wsh  = (float*)smem_raw;
    u64*   Md   = (u64*)(smem_raw + 98304);
    u64*   CTd  = (u64*)(smem_raw + 131072);
    u64*   Cbuf = (u64*)(smem_raw + 147456);

    int tid  = threadIdx.x;
    int lane = tid & 31;
    int warp = tid >> 5;
    u64* wbuf = Cbuf + warp * 256;

    // Cooperative shared loads
    {
        const float4* Wg4 = (const float4*)Wang;
        float4* Wsh4 = (float4*)Wsh;
        for (int idx = tid; idx < NQ * IN_DIM / 4; idx += THREADS) Wsh4[idx] = Wg4[idx];
        const u64* Mg = (const u64*)g_MT;
        for (int idx = tid; idx < DIM * DIM; idx += THREADS) Md[idx] = Mg[idx];
        const float* Cg = (const float*)g_CT;
        for (int idx = tid; idx < DIM * NH; idx += THREADS) {
            float c = Cg[idx];
            CTd[idx] = pack2(c, c);
        }
    }
    __syncthreads();

    float ba[NQ];
#pragma unroll
    for (int w = 0; w < NQ; w++) ba[w] = bang[w];
    float bp = bpost[lane];

    for (int group = blockIdx.x * WARPS + warp; group < NGROUPS;
         group += GRID * WARPS) {
        // 4 contiguous rows; one base pointer, rows at +r*1024 ulonglong2
        const ulonglong2* p =
            (const ulonglong2*)(sv + (size_t)group * ROWS_PER_GROUP * IN_DIM) + lane;

        // ---- Phase 1: angles GEMM, 4 rows, W from shared ----
        u64 acc[ROWS_PER_GROUP][NQ];
#pragma unroll
        for (int r = 0; r < ROWS_PER_GROUP; r++)
#pragma unroll
            for (int w = 0; w < NQ; w++) acc[r][w] = 0ull;

        ulonglong2 cur[ROWS_PER_GROUP], nxt[ROWS_PER_GROUP];
#pragma unroll
        for (int r = 0; r < ROWS_PER_GROUP; r++) cur[r] = p[r * 1024];

#pragma unroll 1
        for (int k = 0; k < 32; k++) {
            if (k < 31) {
#pragma unroll
                for (int r = 0; r < ROWS_PER_GROUP; r++)
                    nxt[r] = p[(k + 1) * 32 + r * 1024];
            }
            const float* wk = Wsh + k * 128 + lane * 4;
#pragma unroll
            for (int w = 0; w < NQ; w++) {
                ulonglong2 wv = *(const ulonglong2*)(wk + w * IN_DIM);
#pragma unroll
                for (int r = 0; r < ROWS_PER_GROUP; r++) {
                    fma2(acc[r][w], cur[r].x, wv.x);
                    fma2(acc[r][w], cur[r].y, wv.y);
                }
            }
#pragma unroll
            for (int r = 0; r < ROWS_PER_GROUP; r++) cur[r] = nxt[r];
        }

        // ---- Reduce + angles -> (cos, sin), per row ----
        float cs[ROWS_PER_GROUP][NQ], sn[ROWS_PER_GROUP][NQ];
#pragma unroll
        for (int r = 0; r < ROWS_PER_GROUP; r++) {
#pragma unroll
            for (int w = 0; w < NQ; w++) {
                float lo, hi;
                unpack2(acc[r][w], lo, hi);
                float v = lo + hi;
#pragma unroll
                for (int off = 16; off; off >>= 1)
                    v += __shfl_xor_sync(0xFFFFFFFFu, v, off);
                float ang = (v + ba[w]) * 0.5f;
                cs[r][w] = __cosf(ang);
                sn[r][w] = __sinf(ang);
            }
        }

        // ---- Product state per row; lane owns amplitudes lane, lane+32 ----
        __syncwarp();
#pragma unroll
        for (int r = 0; r < ROWS_PER_GROUP; r++) {
            float t = 1.f;
#pragma unroll
            for (int w = 1; w < NQ; w++) {
                int bit = (lane >> (NQ - 1 - w)) & 1;
                t *= bit ? sn[r][w] : cs[r][w];
            }
            float e0 = cs[r][0] * t, e1 = sn[r][0] * t;
            wbuf[r * 64 + lane]      = pack2(e0, e0);
            wbuf[r * 64 + lane + 32] = pack2(e1, e1);
        }
        __syncwarp();

        // ---- Phase 2: complex matvec v = M @ s0, 4 rows ----
        u64 am[ROWS_PER_GROUP][2];
#pragma unroll
        for (int r = 0; r < ROWS_PER_GROUP; r++) { am[r][0] = 0ull; am[r][1] = 0ull; }
#pragma unroll 4
        for (int jj = 0; jj < DIM; jj++) {
            u64 m0 = Md[jj * 64 + lane];
            u64 m1 = Md[jj * 64 + lane + 32];
#pragma unroll
            for (int r = 0; r < ROWS_PER_GROUP; r++) {
                u64 s = wbuf[r * 64 + jj];   // broadcast
                fma2(am[r][0], m0, s);
                fma2(am[r][1], m1, s);
            }
        }
        float pr[ROWS_PER_GROUP][2];
#pragma unroll
        for (int r = 0; r < ROWS_PER_GROUP; r++) {
            float re, im;
            unpack2(am[r][0], re, im); pr[r][0] = re * re + im * im;
            unpack2(am[r][1], re, im); pr[r][1] = re * re + im * im;
        }

        // ---- probs into shared as (rowA,rowB) / (rowC,rowD) pairs ----
        __syncwarp();
        wbuf[lane]           = pack2(pr[0][0], pr[1][0]);
        wbuf[lane + 32]      = pack2(pr[0][1], pr[1][1]);
        wbuf[64 + lane]      = pack2(pr[2][0], pr[3][0]);
        wbuf[64 + lane + 32] = pack2(pr[2][1], pr[3][1]);
        __syncwarp();

        // ---- Phase 3: logits = C @ probs + b_post; lane owns head lane ----
        u64 accAB = pack2(bp, bp);
        u64 accCD = pack2(bp, bp);
#pragma unroll 4
        for (int jj = 0; jj < DIM; jj++) {
            u64 c = CTd[jj * NH + lane];
            fma2(accAB, c, wbuf[jj]);
            fma2(accCD, c, wbuf[64 + jj]);
        }
        float lA, lB, lC, lD;
        unpack2(accAB, lA, lB);
        unpack2(accCD, lC, lD);
        size_t ob = (size_t)group * ROWS_PER_GROUP * NH + lane;
        out[ob]          = 1.f + 0.5f * tanhf(lA);
        out[ob + NH]     = 1.f + 0.5f * tanhf(lB);
        out[ob + 2 * NH] = 1.f + 0.5f * tanhf(lC);
        out[ob + 3 * NH] = 1.f + 0.5f * tanhf(lD);
        __syncwarp();  // protect wbuf before next group's writes
    }
}

extern "C" void kernel_launch(void* const* d_in, const int* in_sizes, int n_in,
                              void* d_out, int out_size) {
    const float* sv    = (const float*)d_in[0];
    const float* Wang  = (const float*)d_in[1];
    const float* bang  = (const float*)d_in[2];
    const float* Wpost = (const float*)d_in[3];
    const float* bpost = (const float*)d_in[4];
    const float* qw    = (const float*)d_in[5];
    float* out = (float*)d_out;

    cudaFuncSetAttribute(qag_main, cudaFuncAttributeMaxDynamicSharedMemorySize,
                         SMEM_BYTES);
    setup_kernel<<<1, THREADS>>>(qw, Wpost);
    qag_main<<<GRID, THREADS, SMEM_BYTES>>>(sv, Wang, bang, bpost, out);
}